// round 3
// baseline (speedup 1.0000x reference)
#include <cuda_runtime.h>
#include <math.h>
#include <stdint.h>

// Problem constants
#define NB 16
#define HF 1080
#define WF 1920
#define H2 540
#define W2 960
#define HWF (HF*WF)
#define HW2 (H2*W2)
#define NG 9802
#define NSV 600

// Scratch (allocation-free: __device__ globals; referenced ONLY from device code)
__device__ float d_y[NB*HWF];        // full-scale luma
__device__ float d_xn[NB*HWF];       // full-scale MSCN
__device__ float d_tmpR[NB*H2*WF];   // height-resized intermediate
__device__ float d_y2[NB*HW2];       // half-scale luma
__device__ float d_xn2[NB*HW2];      // half-scale MSCN
__device__ double d_acc[NB*44];      // 22 sums per scale per image
__device__ float d_gtab[NG];
__device__ float d_rtab[NG];
__device__ float d_gw[7];

// Feature ranges (lo, hi) hardcoded from reference
__constant__ float c_lo[36] = {
 0.338f, 0.017204f, 0.236f, -0.123884f, 0.000155f, 0.001122f, 0.244f, -0.123586f,
 0.000152f, 0.000975f, 0.249f, -0.135687f, 0.000174f, 0.000913f, 0.258f, -0.143408f,
 0.000179f, 0.000888f, 0.471f, 0.012809f, 0.218f, -0.094876f, 1.5e-05f, 0.001272f,
 0.222f, -0.115772f, 1.6e-05f, 0.001374f, 0.227f, -0.117188f, 3e-05f, 0.001122f,
 0.228f, -0.12243f, 2.8e-05f, 0.001118f };
__constant__ float c_hi[36] = {
 10.0f, 0.806612f, 1.642f, 0.20293f, 0.712298f, 0.470257f, 1.641f, 0.179083f,
 0.710456f, 0.470984f, 1.555f, 0.100858f, 0.684173f, 0.534174f, 1.561f, 0.100486f,
 0.685696f, 0.536508f, 3.264f, 0.703171f, 1.046f, 0.187459f, 0.442057f, 0.40803f,
 1.042f, 0.162604f, 0.444362f, 0.40243f, 0.996f, 0.098323f, 0.531903f, 0.369589f,
 0.99f, 0.098658f, 0.530092f, 0.370399f };

// ---------------------------------------------------------------------------
// init tables
// ---------------------------------------------------------------------------
__global__ void table_kernel() {
    int i = blockIdx.x * blockDim.x + threadIdx.x;
    if (i < NG) {
        double gd = 0.2 + 0.001 * (double)i;
        float gf = (float)gd;
        d_gtab[i] = gf;
        float q2 = 2.0f / gf, q1 = 1.0f / gf, q3 = 3.0f / gf;
        double r = exp(2.0 * lgamma((double)q2) - lgamma((double)q1) - lgamma((double)q3));
        d_rtab[i] = (float)r;
    }
    if (blockIdx.x == 0 && threadIdx.x == 0) {
        double t[7], s = 0.0;
        double sig = 7.0 / 6.0;
        for (int j = 0; j < 7; j++) {
            double dd = (double)(j - 3);
            t[j] = exp(-dd*dd / (2.0*sig*sig));
            s += t[j];
        }
        for (int j = 0; j < 7; j++) d_gw[j] = (float)(t[j] / s);
    }
}

__global__ void zero_acc_kernel() {
    int i = blockIdx.x * blockDim.x + threadIdx.x;
    if (i < NB*44) d_acc[i] = 0.0;
}

// ---------------------------------------------------------------------------
// luma: y = 255*(.299 r + .587 g + .114 b)   (x is a harness pointer: OK as arg)
// ---------------------------------------------------------------------------
__global__ void luma_kernel(const float* __restrict__ x) {
    int idx = blockIdx.x * blockDim.x + threadIdx.x;
    if (idx >= NB*HWF) return;
    int n = idx / HWF;
    int p = idx - n * HWF;
    const float* base = x + (size_t)n * 3 * HWF;
    float r = base[p], g = base[p + HWF], b = base[p + 2*HWF];
    d_y[idx] = (r*0.299f + g*0.587f + b*0.114f) * 255.0f;
}

// ---------------------------------------------------------------------------
// fused separable 7x7 gaussian -> MSCN (zero padding 'SAME')
// scratch selected by template — no device symbols cross host boundary
// ---------------------------------------------------------------------------
template<int SC>
__global__ void norm_kernel() {
    const int H = SC ? H2 : HF;
    const int W = SC ? W2 : WF;
    const float* in  = SC ? d_y2 : d_y;
    float*       out = SC ? d_xn2 : d_xn;

    __shared__ float sIn[38][40];
    __shared__ float sA[38][33];
    __shared__ float sB[38][33];
    int n = blockIdx.z;
    const float* img = in + (size_t)n * H * W;
    float* oimg = out + (size_t)n * H * W;
    int tx = threadIdx.x, ty = threadIdx.y;
    int t = ty * 32 + tx;
    int bx0 = blockIdx.x * 32, by0 = blockIdx.y * 32;
    float gw[7];
    #pragma unroll
    for (int j = 0; j < 7; j++) gw[j] = d_gw[j];

    for (int i = t; i < 38*38; i += 256) {
        int r = i / 38, c = i - 38*r;
        int gy = by0 - 3 + r, gx = bx0 - 3 + c;
        float v = (gy >= 0 && gy < H && gx >= 0 && gx < W) ? img[gy*W + gx] : 0.0f;
        sIn[r][c] = v;
    }
    __syncthreads();
    for (int i = t; i < 38*32; i += 256) {
        int r = i >> 5, c = i & 31;
        float a = 0.f, b = 0.f;
        #pragma unroll
        for (int j = 0; j < 7; j++) {
            float v = sIn[r][c + j];
            a += gw[j] * v;
            b += gw[j] * v * v;
        }
        sA[r][c] = a; sB[r][c] = b;
    }
    __syncthreads();
    for (int rr = ty; rr < 32; rr += 8) {
        float mu = 0.f, m2 = 0.f;
        #pragma unroll
        for (int j = 0; j < 7; j++) {
            mu += gw[j] * sA[rr + j][tx];
            m2 += gw[j] * sB[rr + j][tx];
        }
        int gy = by0 + rr, gx = bx0 + tx;
        if (gy < H && gx < W) {
            float yv = sIn[rr + 3][tx + 3];
            float sig = sqrtf(fabsf(m2 - mu*mu) + 1e-8f);
            oimg[gy*W + gx] = (yv - mu) / (sig + 1.0f);
        }
    }
}

// ---------------------------------------------------------------------------
// reduction: 22 sums per image (GGD: 2; 4 wrapped-shift AGGD products: 5 each)
// per shift: [cl, cr, sum_neg_p2, sum_pos_p2, sum_abs]
// ---------------------------------------------------------------------------
template<int SC>
__global__ void reduce_kernel() {
    const int H = SC ? H2 : HF;
    const int W = SC ? W2 : WF;
    const int accOff = SC * 22;
    const float* xn = SC ? d_xn2 : d_xn;

    int n = blockIdx.y;
    const float* img = xn + (size_t)n * H * W;
    int HW = H * W;
    float a[22];
    #pragma unroll
    for (int k = 0; k < 22; k++) a[k] = 0.f;
    int tid = threadIdx.x;
    for (int idx = blockIdx.x * blockDim.x + tid; idx < HW; idx += gridDim.x * blockDim.x) {
        int h = idx / W;
        int w = idx - h * W;
        float v = img[idx];
        a[0] += v * v;
        a[1] += fabsf(v);
        int wm1 = (w == 0) ? W - 1 : w - 1;
        int hm1 = (h == 0) ? H - 1 : h - 1;
        int hp1 = (h == H - 1) ? 0 : h + 1;
        float nbs[4];
        nbs[0] = img[h*W + wm1];     // roll (0,1)
        nbs[1] = img[hm1*W + w];     // roll (1,0)
        nbs[2] = img[hm1*W + wm1];   // roll (1,1)
        nbs[3] = img[hp1*W + wm1];   // roll (-1,1)
        #pragma unroll
        for (int s = 0; s < 4; s++) {
            float p = v * nbs[s];
            float p2 = p * p;
            int o = 2 + 5 * s;
            if (p < 0.f)      { a[o+0] += 1.f; a[o+2] += p2; }
            else if (p > 0.f) { a[o+1] += 1.f; a[o+3] += p2; }
            a[o+4] += fabsf(p);
        }
    }
    __shared__ float red[8][22];
    int lane = tid & 31, wid = tid >> 5;
    #pragma unroll
    for (int k = 0; k < 22; k++) {
        float v = a[k];
        for (int off = 16; off > 0; off >>= 1) v += __shfl_down_sync(0xffffffffu, v, off);
        if (lane == 0) red[wid][k] = v;
    }
    __syncthreads();
    if (tid < 22) {
        float s = 0.f;
        #pragma unroll
        for (int wv = 0; wv < 8; wv++) s += red[wv][tid];
        atomicAdd(&d_acc[n*44 + accOff + tid], (double)s);
    }
}

// ---------------------------------------------------------------------------
// bicubic antialiased downsample by 2: fixed 8-tap filter, mirror boundary
// weights = {-3,-9,29,111,111,29,-9,-3}/256 (exact, from _resize_matrix at s=0.5)
// ---------------------------------------------------------------------------
__device__ __forceinline__ int mirr(int s, int n) {
    if (s < 0) return -1 - s;
    if (s >= n) return 2*n - 1 - s;
    return s;
}
__constant__ float c_wq[8] = { -0.01171875f, -0.03515625f, 0.11328125f, 0.43359375f,
                                0.43359375f, 0.11328125f, -0.03515625f, -0.01171875f };

__global__ void resize_h_kernel() {
    int idx = blockIdx.x * blockDim.x + threadIdx.x;
    const int total = NB * H2 * WF;
    if (idx >= total) return;
    int w = idx % WF;
    int t = idx / WF;
    int o = t % H2;
    int n = t / H2;
    const float* img = d_y + (size_t)n * HWF;
    int b = 2*o - 3;
    float s = 0.f;
    #pragma unroll
    for (int j = 0; j < 8; j++) {
        int r = mirr(b + j, HF);
        s += c_wq[j] * img[r*WF + w];
    }
    d_tmpR[idx] = s;
}

__global__ void resize_w_kernel() {
    int idx = blockIdx.x * blockDim.x + threadIdx.x;
    const int total = NB * HW2;
    if (idx >= total) return;
    int p = idx % W2;
    int t = idx / W2;
    int o = t % H2;
    int n = t / H2;
    const float* row = d_tmpR + ((size_t)n * H2 + o) * WF;
    int b = 2*p - 3;
    float s = 0.f;
    #pragma unroll
    for (int j = 0; j < 8; j++) {
        int c = mirr(b + j, WF);
        s += c_wq[j] * row[c];
    }
    d_y2[idx] = s;
}

// ---------------------------------------------------------------------------
// final: features from sums (block-parallel argmin over gamma table) + RBF-SVM
// ---------------------------------------------------------------------------
__device__ int block_argmin(float target, float* sval, int* sidx) {
    int tid = threadIdx.x;
    float best = 3.4e38f;
    int bi = 0;
    for (int i = tid; i < NG; i += 256) {
        float dd = fabsf(target - d_rtab[i]);
        if (dd < best) { best = dd; bi = i; }   // ascending i -> keeps first on ties
    }
    sval[tid] = best; sidx[tid] = bi;
    __syncthreads();
    for (int s = 128; s > 0; s >>= 1) {
        if (tid < s) {
            float v2 = sval[tid + s]; int i2 = sidx[tid + s];
            if (v2 < sval[tid] || (v2 == sval[tid] && i2 < sidx[tid])) {
                sval[tid] = v2; sidx[tid] = i2;
            }
        }
        __syncthreads();
    }
    int res = sidx[0];
    __syncthreads();
    return res;
}

__global__ void final_kernel(const float* __restrict__ sv,
                             const float* __restrict__ coef,
                             float* __restrict__ out) {
    __shared__ double sacc[44];
    __shared__ float feats[36];
    __shared__ float sf[36];
    __shared__ float sval[256];
    __shared__ int   sidx[256];
    int n = blockIdx.x;
    int tid = threadIdx.x;
    if (tid < 44) sacc[tid] = d_acc[n*44 + tid];
    __syncthreads();

    for (int sc = 0; sc < 2; sc++) {
        double M = sc ? (double)HW2 : (double)HWF;
        int base = sc * 22, fb = sc * 18;
        // GGD
        double s2 = sacc[base + 0] / M;
        double E  = sacc[base + 1] / M;
        float rho = (float)(s2 / (E * E));
        int idx = block_argmin(rho, sval, sidx);
        if (tid == 0) {
            feats[fb + 0] = d_gtab[idx];
            float sq = sqrtf((float)s2);
            feats[fb + 1] = sq * sq;
        }
        // AGGD for 4 shifts
        for (int t4 = 0; t4 < 4; t4++) {
            int o = base + 2 + 5 * t4;
            double cl = sacc[o+0], cr = sacc[o+1];
            double sn = sacc[o+2], sp = sacc[o+3], sa = sacc[o+4];
            double sl = sqrt(sn / cl), sr = sqrt(sp / cr);
            double gh = sl / sr;
            double rhat = (sa / M) * (sa / M) / ((sn + sp) / M);
            double rhn = rhat * (gh*gh*gh + 1.0) * (gh + 1.0)
                         / ((gh*gh + 1.0) * (gh*gh + 1.0));
            int id2 = block_argmin((float)rhn, sval, sidx);
            if (tid == 0) {
                double aa = (double)d_gtab[id2];
                double eta = (sr - sl) *
                    exp(lgamma(2.0/aa) - 0.5*(lgamma(1.0/aa) + lgamma(3.0/aa)));
                feats[fb + 2 + 4*t4 + 0] = (float)aa;
                feats[fb + 2 + 4*t4 + 1] = (float)eta;
                feats[fb + 2 + 4*t4 + 2] = (float)(sl * sl);
                feats[fb + 2 + 4*t4 + 3] = (float)(sr * sr);
            }
            __syncthreads();
        }
    }
    __syncthreads();
    if (tid < 36) sf[tid] = -1.0f + 2.0f * (feats[tid] - c_lo[tid]) / (c_hi[tid] - c_lo[tid]);
    __syncthreads();

    float local = 0.f;
    for (int k = tid; k < NSV; k += 256) {
        const float* svk = sv + k * 36;
        float dist = 0.f;
        #pragma unroll
        for (int d = 0; d < 36; d++) {
            float df = sf[d] - svk[d];
            dist += df * df;
        }
        local += expf(-0.05f * dist) * coef[k];
    }
    sval[tid] = local;
    __syncthreads();
    for (int s = 128; s > 0; s >>= 1) {
        if (tid < s) sval[tid] += sval[tid + s];
        __syncthreads();
    }
    if (tid == 0) out[n] = sval[0] + 153.591f;
}

// ---------------------------------------------------------------------------
extern "C" void kernel_launch(void* const* d_in, const int* in_sizes, int n_in,
                              void* d_out, int out_size) {
    const float* x    = (const float*)d_in[0];   // (16,3,1080,1920)
    const float* sv   = (const float*)d_in[1];   // (600,36)
    const float* coef = (const float*)d_in[2];   // (600,)
    float* out = (float*)d_out;                  // (16,)

    table_kernel<<<(NG + 255) / 256, 256>>>();
    zero_acc_kernel<<<1, 256>>>();

    luma_kernel<<<(NB*HWF + 255) / 256, 256>>>(x);

    // full-scale MSCN + reduce
    {
        dim3 g((WF + 31) / 32, (HF + 31) / 32, NB);
        norm_kernel<0><<<g, dim3(32, 8)>>>();
    }
    reduce_kernel<0><<<dim3(1024, NB), 256>>>();

    // half-scale: resize, MSCN, reduce
    resize_h_kernel<<<(NB*H2*WF + 255) / 256, 256>>>();
    resize_w_kernel<<<(NB*HW2 + 255) / 256, 256>>>();
    {
        dim3 g((W2 + 31) / 32, (H2 + 31) / 32, NB);
        norm_kernel<1><<<g, dim3(32, 8)>>>();
    }
    reduce_kernel<1><<<dim3(256, NB), 256>>>();

    final_kernel<<<NB, 256>>>(sv, coef, out);
}

// round 4
// speedup vs baseline: 1.2647x; 1.2647x over previous
#include <cuda_runtime.h>
#include <math.h>
#include <stdint.h>

// Problem constants
#define NB 16
#define HF 1080
#define WF 1920
#define H2 540
#define W2 960
#define HWF (HF*WF)
#define HW2 (H2*W2)
#define NG 9802
#define NSV 600

typedef unsigned long long u64;

// Scratch (__device__ globals; referenced ONLY from device code)
__device__ float d_y[NB*HWF];        // full-scale luma
__device__ float d_xn[NB*HWF];       // full-scale MSCN
__device__ float d_y2[NB*HW2];       // half-scale luma
__device__ float d_xn2[NB*HW2];      // half-scale MSCN
__device__ double d_acc[NB*44];      // 22 sums per scale per image
__device__ float d_gtab[NG];
__device__ float d_rtab[NG];
__device__ float d_gw[7];

// Feature ranges (lo, hi)
__constant__ float c_lo[36] = {
 0.338f, 0.017204f, 0.236f, -0.123884f, 0.000155f, 0.001122f, 0.244f, -0.123586f,
 0.000152f, 0.000975f, 0.249f, -0.135687f, 0.000174f, 0.000913f, 0.258f, -0.143408f,
 0.000179f, 0.000888f, 0.471f, 0.012809f, 0.218f, -0.094876f, 1.5e-05f, 0.001272f,
 0.222f, -0.115772f, 1.6e-05f, 0.001374f, 0.227f, -0.117188f, 3e-05f, 0.001122f,
 0.228f, -0.12243f, 2.8e-05f, 0.001118f };
__constant__ float c_hi[36] = {
 10.0f, 0.806612f, 1.642f, 0.20293f, 0.712298f, 0.470257f, 1.641f, 0.179083f,
 0.710456f, 0.470984f, 1.555f, 0.100858f, 0.684173f, 0.534174f, 1.561f, 0.100486f,
 0.685696f, 0.536508f, 3.264f, 0.703171f, 1.046f, 0.187459f, 0.442057f, 0.40803f,
 1.042f, 0.162604f, 0.444362f, 0.40243f, 0.996f, 0.098323f, 0.531903f, 0.369589f,
 0.99f, 0.098658f, 0.530092f, 0.370399f };

// 8-tap dyadic bicubic downsample weights = {-3,-9,29,111,111,29,-9,-3}/256
__constant__ float c_wq[8] = { -0.01171875f, -0.03515625f, 0.11328125f, 0.43359375f,
                                0.43359375f, 0.11328125f, -0.03515625f, -0.01171875f };

// ---------------------------------------------------------------------------
// packed f32x2 helpers (sm_103a FFMA2)
// ---------------------------------------------------------------------------
__device__ __forceinline__ u64 pack2(float lo, float hi) {
    u64 r;
    asm("mov.b64 %0, {%1, %2};" : "=l"(r) : "f"(lo), "f"(hi));
    return r;
}
__device__ __forceinline__ void unpack2(u64 v, float &lo, float &hi) {
    asm("mov.b64 {%0, %1}, %2;" : "=f"(lo), "=f"(hi) : "l"(v));
}
__device__ __forceinline__ void ffma2(u64 &acc, u64 a, u64 b) {
    asm("fma.rn.f32x2 %0, %1, %2, %0;" : "+l"(acc) : "l"(a), "l"(b));
}

// ---------------------------------------------------------------------------
// init: tables (f32 lgamma), gaussian weights, zero accumulators
// ---------------------------------------------------------------------------
__global__ void table_kernel() {
    int i = blockIdx.x * blockDim.x + threadIdx.x;
    if (i < NG) {
        double gd = 0.2 + 0.001 * (double)i;
        float gf = (float)gd;
        d_gtab[i] = gf;
        float q2 = 2.0f / gf, q1 = 1.0f / gf, q3 = 3.0f / gf;
        d_rtab[i] = expf(2.0f * lgammaf(q2) - lgammaf(q1) - lgammaf(q3));
    }
    if (blockIdx.x == 0) {
        for (int k = threadIdx.x; k < NB*44; k += blockDim.x) d_acc[k] = 0.0;
        if (threadIdx.x == 0) {
            double t[7], s = 0.0;
            double sig = 7.0 / 6.0;
            for (int j = 0; j < 7; j++) {
                double dd = (double)(j - 3);
                t[j] = exp(-dd*dd / (2.0*sig*sig));
                s += t[j];
            }
            for (int j = 0; j < 7; j++) d_gw[j] = (float)(t[j] / s);
        }
    }
}

// ---------------------------------------------------------------------------
// luma (float4): y = 255*(.299 r + .587 g + .114 b)
// ---------------------------------------------------------------------------
#define HWF4 (HWF/4)
__global__ void luma_kernel(const float* __restrict__ x) {
    int idx = blockIdx.x * blockDim.x + threadIdx.x;
    if (idx >= NB*HWF4) return;
    int n = idx / HWF4;
    int p = idx - n * HWF4;
    const float4* bx = (const float4*)(x + (size_t)n * 3 * HWF);
    float4 r = bx[p];
    float4 g = bx[p + HWF4];
    float4 b = bx[p + 2*HWF4];
    float4 o;
    o.x = (r.x*0.299f + g.x*0.587f + b.x*0.114f) * 255.0f;
    o.y = (r.y*0.299f + g.y*0.587f + b.y*0.114f) * 255.0f;
    o.z = (r.z*0.299f + g.z*0.587f + b.z*0.114f) * 255.0f;
    o.w = (r.w*0.299f + g.w*0.587f + b.w*0.114f) * 255.0f;
    ((float4*)d_y)[(size_t)n * HWF4 + p] = o;
}

// ---------------------------------------------------------------------------
// fused separable 7x7 gaussian -> MSCN, packed (v,v^2) f32x2 pipeline
// 32x32 output tile, 6-halo
// ---------------------------------------------------------------------------
template<int SC>
__global__ __launch_bounds__(256) void norm_kernel() {
    const int H = SC ? H2 : HF;
    const int W = SC ? W2 : WF;
    const float* in  = SC ? d_y2 : d_y;
    float*       out = SC ? d_xn2 : d_xn;

    __shared__ u64 sIn[38][40];   // (v, v^2) packed
    __shared__ u64 sAB[38][36];   // (a, b) packed horizontal results

    int n = blockIdx.z;
    const float* img = in + (size_t)n * H * W;
    float* oimg = out + (size_t)n * H * W;
    int tx = threadIdx.x & 31, ty = threadIdx.x >> 5;
    int t = threadIdx.x;
    int bx0 = blockIdx.x * 32, by0 = blockIdx.y * 32;

    u64 gw2[7];
    #pragma unroll
    for (int j = 0; j < 7; j++) { float w = d_gw[j]; gw2[j] = pack2(w, w); }

    // load tile + halo; zero pad
    for (int i = t; i < 38*38; i += 256) {
        int r = i / 38, c = i - 38*r;
        int gy = by0 - 3 + r, gx = bx0 - 3 + c;
        float v = (gy >= 0 && gy < H && gx >= 0 && gx < W) ? img[gy*W + gx] : 0.0f;
        sIn[r][c] = pack2(v, v*v);
    }
    __syncthreads();

    // horizontal pass: 38 rows x 8 chunks of 4 outputs
    for (int i = t; i < 38*8; i += 256) {
        int r = i >> 3, c4 = (i & 7) << 2;
        u64 vp[10];
        const ulonglong2* q = (const ulonglong2*)&sIn[r][c4];
        #pragma unroll
        for (int k = 0; k < 5; k++) { ulonglong2 e = q[k]; vp[2*k] = e.x; vp[2*k+1] = e.y; }
        u64 acc[4];
        #pragma unroll
        for (int cc = 0; cc < 4; cc++) {
            u64 a = 0ull;
            #pragma unroll
            for (int j = 0; j < 7; j++) ffma2(a, vp[cc+j], gw2[j]);
            acc[cc] = a;
        }
        ulonglong2* qo = (ulonglong2*)&sAB[r][c4];
        qo[0] = make_ulonglong2(acc[0], acc[1]);
        qo[1] = make_ulonglong2(acc[2], acc[3]);
    }
    __syncthreads();

    // vertical pass: each thread does 4 consecutive rows at column tx
    int rr0 = ty * 4;
    u64 s[10];
    #pragma unroll
    for (int k = 0; k < 10; k++) s[k] = sAB[rr0 + k][tx];
    #pragma unroll
    for (int k = 0; k < 4; k++) {
        u64 m = 0ull;
        #pragma unroll
        for (int j = 0; j < 7; j++) ffma2(m, s[k+j], gw2[j]);
        float mu, m2;
        unpack2(m, mu, m2);
        int gy = by0 + rr0 + k;
        if (gy < H) {
            float yv, yv2;
            unpack2(sIn[rr0 + k + 3][tx + 3], yv, yv2);
            float sv = fabsf(m2 - mu*mu) + 1e-8f;
            float sig = sv * rsqrtf(sv);
            oimg[gy*W + bx0 + tx] = __fdividef(yv - mu, sig + 1.0f);
        }
    }
}

// ---------------------------------------------------------------------------
// reduction: warp-per-row walker; 22 sums per image
// per shift: [cl, cr, sum_neg_p2, sum_pos_p2, sum_abs]
// shifts in order: (0,1)=left, (1,0)=up, (1,1)=up-left, (-1,1)=down-left
// ---------------------------------------------------------------------------
__device__ __forceinline__ void prod_acc(float* a, int s, float p) {
    int o = 2 + 5*s;
    float p2 = p * p;
    if (p < 0.f)      { a[o+0] += 1.f; a[o+2] += p2; }
    else if (p > 0.f) { a[o+1] += 1.f; a[o+3] += p2; }
    a[o+4] += fabsf(p);
}
__device__ __forceinline__ void pix_acc(float* a, float v, float lf, float up,
                                        float ul, float dl) {
    a[0] += v * v;
    a[1] += fabsf(v);
    prod_acc(a, 0, v * lf);
    prod_acc(a, 1, v * up);
    prod_acc(a, 2, v * ul);
    prod_acc(a, 3, v * dl);
}

template<int SC>
__global__ __launch_bounds__(256) void reduce_kernel() {
    const int H = SC ? H2 : HF;
    const int W = SC ? W2 : WF;
    const int accOff = SC * 22;
    const float* base = SC ? d_xn2 : d_xn;

    int n = blockIdx.y;
    int lane = threadIdx.x & 31, wid = threadIdx.x >> 5;
    int h = blockIdx.x * 8 + wid;

    float a[22];
    #pragma unroll
    for (int k = 0; k < 22; k++) a[k] = 0.f;

    if (h < H) {
        const float* img = base + (size_t)n * H * W;
        const float* cur  = img + (size_t)h * W;
        const float* up   = img + (size_t)((h == 0) ? H-1 : h-1) * W;
        const float* down = img + (size_t)((h == H-1) ? 0 : h+1) * W;
        float cc = cur[W-1], cu = up[W-1], cd = down[W-1];   // wrap carries
        for (int w0 = 0; w0 < W; w0 += 64) {
            int off = w0 + 2*lane;
            float2 c = *(const float2*)(cur + off);
            float2 u = *(const float2*)(up + off);
            float2 d = *(const float2*)(down + off);
            float lc = __shfl_up_sync(0xffffffffu, c.y, 1);
            float lu = __shfl_up_sync(0xffffffffu, u.y, 1);
            float ld = __shfl_up_sync(0xffffffffu, d.y, 1);
            if (lane == 0) { lc = cc; lu = cu; ld = cd; }
            // even pixel (w0+2*lane): left=lc, up=u.x, upleft=lu, downleft=ld
            pix_acc(a, c.x, lc, u.x, lu, ld);
            // odd pixel: left=c.x, up=u.y, upleft=u.x, downleft=d.x
            pix_acc(a, c.y, c.x, u.y, u.x, d.x);
            cc = __shfl_sync(0xffffffffu, c.y, 31);
            cu = __shfl_sync(0xffffffffu, u.y, 31);
            cd = __shfl_sync(0xffffffffu, d.y, 31);
        }
    }

    __shared__ float red[8][22];
    #pragma unroll
    for (int k = 0; k < 22; k++) {
        float v = a[k];
        for (int off = 16; off > 0; off >>= 1) v += __shfl_down_sync(0xffffffffu, v, off);
        if (lane == 0) red[wid][k] = v;
    }
    __syncthreads();
    if (threadIdx.x < 22) {
        float s = 0.f;
        #pragma unroll
        for (int wv = 0; wv < 8; wv++) s += red[wv][threadIdx.x];
        atomicAdd(&d_acc[n*44 + accOff + threadIdx.x], (double)s);
    }
}

// ---------------------------------------------------------------------------
// fused bicubic downsample by 2 (both axes) with mirror boundary
// out tile 64(w) x 8(h); input tile 134 x 22
// ---------------------------------------------------------------------------
__device__ __forceinline__ int mirr(int s, int nmax) {
    if (s < 0) return -1 - s;
    if (s >= nmax) return 2*nmax - 1 - s;
    return s;
}

__global__ __launch_bounds__(256) void resize_kernel() {
    __shared__ float sy[22][136];
    __shared__ float st[8][136];
    int n = blockIdx.z;
    int o0 = blockIdx.y * 8;
    int p0 = blockIdx.x * 64;
    int rb = 2*o0 - 3, cb = 2*p0 - 3;
    int t = threadIdx.x;
    const float* img = d_y + (size_t)n * HWF;

    for (int i = t; i < 22*134; i += 256) {
        int rl = i / 134, cl = i - 134*rl;
        sy[rl][cl] = img[mirr(rb + rl, HF)*WF + mirr(cb + cl, WF)];
    }
    __syncthreads();
    for (int i = t; i < 8*134; i += 256) {
        int ol = i / 134, cl = i - 134*ol;
        float s = 0.f;
        #pragma unroll
        for (int j = 0; j < 8; j++) s += c_wq[j] * sy[2*ol + j][cl];
        st[ol][cl] = s;
    }
    __syncthreads();
    for (int i = t; i < 512; i += 256) {
        int ol = i >> 6, pl = i & 63;
        float s = 0.f;
        #pragma unroll
        for (int j = 0; j < 8; j++) s += c_wq[j] * st[ol][2*pl + j];
        int o = o0 + ol;
        if (o < H2) d_y2[(size_t)n * HW2 + o*W2 + p0 + pl] = s;
    }
}

// ---------------------------------------------------------------------------
// final: features from sums (block-parallel argmin over gamma table) + RBF-SVM
// ---------------------------------------------------------------------------
__device__ int block_argmin(float target, float* sval, int* sidx) {
    int tid = threadIdx.x;
    float best = 3.4e38f;
    int bi = 0;
    for (int i = tid; i < NG; i += 256) {
        float dd = fabsf(target - d_rtab[i]);
        if (dd < best) { best = dd; bi = i; }
    }
    sval[tid] = best; sidx[tid] = bi;
    __syncthreads();
    for (int s = 128; s > 0; s >>= 1) {
        if (tid < s) {
            float v2 = sval[tid + s]; int i2 = sidx[tid + s];
            if (v2 < sval[tid] || (v2 == sval[tid] && i2 < sidx[tid])) {
                sval[tid] = v2; sidx[tid] = i2;
            }
        }
        __syncthreads();
    }
    int res = sidx[0];
    __syncthreads();
    return res;
}

__global__ void final_kernel(const float* __restrict__ sv,
                             const float* __restrict__ coef,
                             float* __restrict__ out) {
    __shared__ double sacc[44];
    __shared__ float feats[36];
    __shared__ float sf[36];
    __shared__ float sval[256];
    __shared__ int   sidx[256];
    int n = blockIdx.x;
    int tid = threadIdx.x;
    if (tid < 44) sacc[tid] = d_acc[n*44 + tid];
    __syncthreads();

    for (int sc = 0; sc < 2; sc++) {
        double M = sc ? (double)HW2 : (double)HWF;
        int base = sc * 22, fb = sc * 18;
        double s2 = sacc[base + 0] / M;
        double E  = sacc[base + 1] / M;
        float rho = (float)(s2 / (E * E));
        int idx = block_argmin(rho, sval, sidx);
        if (tid == 0) {
            feats[fb + 0] = d_gtab[idx];
            float sq = sqrtf((float)s2);
            feats[fb + 1] = sq * sq;
        }
        for (int t4 = 0; t4 < 4; t4++) {
            int o = base + 2 + 5 * t4;
            double cl = sacc[o+0], cr = sacc[o+1];
            double sn = sacc[o+2], sp = sacc[o+3], sa = sacc[o+4];
            double sl = sqrt(sn / cl), sr = sqrt(sp / cr);
            double gh = sl / sr;
            double rhat = (sa / M) * (sa / M) / ((sn + sp) / M);
            double rhn = rhat * (gh*gh*gh + 1.0) * (gh + 1.0)
                         / ((gh*gh + 1.0) * (gh*gh + 1.0));
            int id2 = block_argmin((float)rhn, sval, sidx);
            if (tid == 0) {
                double aa = (double)d_gtab[id2];
                double eta = (sr - sl) *
                    exp(lgamma(2.0/aa) - 0.5*(lgamma(1.0/aa) + lgamma(3.0/aa)));
                feats[fb + 2 + 4*t4 + 0] = (float)aa;
                feats[fb + 2 + 4*t4 + 1] = (float)eta;
                feats[fb + 2 + 4*t4 + 2] = (float)(sl * sl);
                feats[fb + 2 + 4*t4 + 3] = (float)(sr * sr);
            }
            __syncthreads();
        }
    }
    __syncthreads();
    if (tid < 36) sf[tid] = -1.0f + 2.0f * (feats[tid] - c_lo[tid]) / (c_hi[tid] - c_lo[tid]);
    __syncthreads();

    float local = 0.f;
    for (int k = tid; k < NSV; k += 256) {
        const float* svk = sv + k * 36;
        float dist = 0.f;
        #pragma unroll
        for (int d = 0; d < 36; d++) {
            float df = sf[d] - svk[d];
            dist += df * df;
        }
        local += expf(-0.05f * dist) * coef[k];
    }
    sval[tid] = local;
    __syncthreads();
    for (int s = 128; s > 0; s >>= 1) {
        if (tid < s) sval[tid] += sval[tid + s];
        __syncthreads();
    }
    if (tid == 0) out[n] = sval[0] + 153.591f;
}

// ---------------------------------------------------------------------------
extern "C" void kernel_launch(void* const* d_in, const int* in_sizes, int n_in,
                              void* d_out, int out_size) {
    const float* x    = (const float*)d_in[0];   // (16,3,1080,1920)
    const float* sv   = (const float*)d_in[1];   // (600,36)
    const float* coef = (const float*)d_in[2];   // (600,)
    float* out = (float*)d_out;                  // (16,)

    table_kernel<<<(NG + 255) / 256, 256>>>();

    luma_kernel<<<(NB*HWF4 + 255) / 256, 256>>>(x);

    // full-scale MSCN + reduce
    {
        dim3 g(WF/32, (HF + 31) / 32, NB);
        norm_kernel<0><<<g, 256>>>();
    }
    reduce_kernel<0><<<dim3(HF/8, NB), 256>>>();

    // half-scale: fused resize, MSCN, reduce
    resize_kernel<<<dim3(W2/64, (H2 + 7) / 8, NB), 256>>>();
    {
        dim3 g(W2/32, (H2 + 31) / 32, NB);
        norm_kernel<1><<<g, 256>>>();
    }
    reduce_kernel<1><<<dim3((H2 + 7) / 8, NB), 256>>>();

    final_kernel<<<NB, 256>>>(sv, coef, out);
}